// round 13
// baseline (speedup 1.0000x reference)
#include <cuda_runtime.h>
#include <cuda_bf16.h>
#include <cstdint>

#define NN 50000
#define EE 800000
#define FF 128
#define CC 47

// ------------------------- device scratch -------------------------
__device__ float g_agg[NN * FF];
__device__ float g_z[NN * FF];
__device__ float g_h[NN * FF];
__device__ int g_cnt[NN];
__device__ int g_off[NN + 1];
__device__ int g_cur[NN];
__device__ int g_csr[EE];
// weight blobs: [8 gemms][N<=128 rows][K=128 cols] bf16, row-major [n][k] (B^T)
__device__ __align__(16) __nv_bfloat16 g_whi[8][128 * 128];
__device__ __align__(16) __nv_bfloat16 g_wlo[8][128 * 128];
__device__ float g_scale[8][128];
__device__ float g_shift[8][128];

// ------------------------- PTX helpers -------------------------
__device__ __forceinline__ uint32_t smem_u32(const void* p) {
    uint32_t a;
    asm("{ .reg .u64 t; cvta.to.shared.u64 t, %1; cvt.u32.u64 %0, t; }" : "=r"(a) : "l"(p));
    return a;
}
__device__ __forceinline__ void ldsm4(uint32_t& r0, uint32_t& r1, uint32_t& r2, uint32_t& r3,
                                      uint32_t addr) {
    asm volatile("ldmatrix.sync.aligned.m8n8.x4.shared.b16 {%0,%1,%2,%3}, [%4];"
                 : "=r"(r0), "=r"(r1), "=r"(r2), "=r"(r3) : "r"(addr));
}
__device__ __forceinline__ void mma16816(float* c, const uint32_t* a, uint32_t b0, uint32_t b1) {
    asm volatile(
        "mma.sync.aligned.m16n8k16.row.col.f32.bf16.bf16.f32 "
        "{%0,%1,%2,%3}, {%4,%5,%6,%7}, {%8,%9}, {%0,%1,%2,%3};"
        : "+f"(c[0]), "+f"(c[1]), "+f"(c[2]), "+f"(c[3])
        : "r"(a[0]), "r"(a[1]), "r"(a[2]), "r"(a[3]), "r"(b0), "r"(b1));
}
__device__ __forceinline__ void split2(float a, float b, uint32_t& hi, uint32_t& lo) {
    __nv_bfloat16 ha = __float2bfloat16(a), hb = __float2bfloat16(b);
    __nv_bfloat16 la = __float2bfloat16(a - __bfloat162float(ha));
    __nv_bfloat16 lb = __float2bfloat16(b - __bfloat162float(hb));
    hi = (uint32_t)__bfloat16_as_ushort(ha) | ((uint32_t)__bfloat16_as_ushort(hb) << 16);
    lo = (uint32_t)__bfloat16_as_ushort(la) | ((uint32_t)__bfloat16_as_ushort(lb) << 16);
}

// ------------------------- CSR build -------------------------
__global__ void zero_kernel() {
    int i = blockIdx.x * blockDim.x + threadIdx.x;
    if (i < NN) g_cnt[i] = 0;
}
__global__ void hist_kernel(const int* __restrict__ dst) {
    int e = blockIdx.x * blockDim.x + threadIdx.x;
    if (e < EE) atomicAdd(&g_cnt[dst[e]], 1);
}
__global__ void scan_kernel() {
    __shared__ int wsums[32];
    int t = threadIdx.x, lane = t & 31, wid = t >> 5;
    int carry = 0;
    for (int base = 0; base < NN; base += 1024) {
        int i = base + t;
        int v = (i < NN) ? g_cnt[i] : 0;
        int x = v;
        #pragma unroll
        for (int d = 1; d < 32; d <<= 1) {
            int y = __shfl_up_sync(0xffffffffu, x, d);
            if (lane >= d) x += y;
        }
        if (lane == 31) wsums[wid] = x;
        __syncthreads();
        if (wid == 0) {
            int s = wsums[lane];
            #pragma unroll
            for (int d = 1; d < 32; d <<= 1) {
                int y = __shfl_up_sync(0xffffffffu, s, d);
                if (lane >= d) s += y;
            }
            wsums[lane] = s;
        }
        __syncthreads();
        int pre = (wid > 0) ? wsums[wid - 1] : 0;
        int excl = carry + pre + x - v;
        if (i < NN) { g_off[i] = excl; g_cur[i] = excl; }
        carry += wsums[31];
        __syncthreads();
    }
    if (t == 0) g_off[NN] = carry;
}
__global__ void scatter_kernel(const int* __restrict__ src, const int* __restrict__ dst) {
    int e = blockIdx.x * blockDim.x + threadIdx.x;
    if (e < EE) {
        int p = atomicAdd(&g_cur[dst[e]], 1);
        g_csr[p] = src[e];
    }
}

// ------------------------- aggregation (warp per node) -------------------------
__device__ __forceinline__ void add4(float4& a, const float4& b) {
    a.x += b.x; a.y += b.y; a.z += b.z; a.w += b.w;
}
__global__ void agg_kernel(const float* __restrict__ x, int layer0) {
    const float* __restrict__ hin = layer0 ? x : g_h;
    int gt = blockIdx.x * blockDim.x + threadIdx.x;
    int node = gt >> 5, lane = gt & 31;
    if (node >= NN) return;
    int s = g_off[node], e = g_off[node + 1];
    float4 a0 = *(const float4*)(hin + (size_t)node * FF + lane * 4);  // self term
    float4 a1 = make_float4(0.f, 0.f, 0.f, 0.f);
    int j = s;
    for (; j + 4 <= e; j += 4) {
        int n0 = g_csr[j], n1 = g_csr[j + 1], n2 = g_csr[j + 2], n3 = g_csr[j + 3];
        float4 v0 = *(const float4*)(hin + (size_t)n0 * FF + lane * 4);
        float4 v1 = *(const float4*)(hin + (size_t)n1 * FF + lane * 4);
        float4 v2 = *(const float4*)(hin + (size_t)n2 * FF + lane * 4);
        float4 v3 = *(const float4*)(hin + (size_t)n3 * FF + lane * 4);
        add4(a0, v0); add4(a1, v1); add4(a0, v2); add4(a1, v3);
    }
    for (; j < e; j++) {
        float4 v = *(const float4*)(hin + (size_t)g_csr[j] * FF + lane * 4);
        add4(a0, v);
    }
    add4(a0, a1);
    *(float4*)(g_agg + (size_t)node * FF + lane * 4) = a0;
}

// ------------------------- weight prep: split/transpose + folded BN -------------------------
__global__ void prep_kernel(const float* __restrict__ W1, const float* __restrict__ b1,
                            const float* __restrict__ gamma, const float* __restrict__ beta,
                            const float* __restrict__ mean, const float* __restrict__ var,
                            const float* __restrict__ W2, const float* __restrict__ b2,
                            const float* __restrict__ lw1, const float* __restrict__ lb1,
                            const float* __restrict__ lw2, const float* __restrict__ lb2) {
    int g = blockIdx.x;          // 0..7
    int tid = threadIdx.x;
    int rows = (g == 7) ? 64 : 128;     // N dimension of this gemm's output
    for (int idx = tid; idx < rows * 128; idx += blockDim.x) {
        int n = idx >> 7, k = idx & 127;
        float v;
        if (g < 6) {
            int li = g >> 1;
            const float* W = (g & 1) ? W2 : W1;
            v = W[((size_t)li * 128 + k) * 128 + n];
        } else if (g == 6) {
            v = lw1[k * 128 + n];
        } else {
            v = (n < CC) ? lw2[k * CC + n] : 0.f;
        }
        __nv_bfloat16 h = __float2bfloat16(v);
        __nv_bfloat16 l = __float2bfloat16(v - __bfloat162float(h));
        g_whi[g][n * 128 + k] = h;    // B^T: [n][k] row-major
        g_wlo[g][n * 128 + k] = l;
    }
    if (tid < 128) {
        float sc = 1.f, sh = 0.f;
        if (g < 6) {
            int li = g >> 1, c = li * 128 + tid;
            if ((g & 1) == 0) {
                float rs = rsqrtf(var[c] + 1e-5f);
                sc = gamma[c] * rs;
                sh = beta[c] + (b1[c] - mean[c]) * sc;
            } else {
                sh = b2[c];
            }
        } else if (g == 6) {
            sh = lb1[tid];
        } else {
            sh = (tid < CC) ? lb2[tid] : 0.f;
        }
        g_scale[g][tid] = sc;
        g_shift[g][tid] = sh;
    }
}

// ------------------------- mma.sync GEMM: [128 x 128] @ [128 x NC], split-bf16 x3 -------------------------
// smem row stride: 136 bf16 = 272 B (16B-aligned, ldmatrix conflict-free: 8 rows
// at +272B land on banks 0,4,8,...,28 -> all 32 banks once per phase).
static constexpr int LDS_B = 272;                 // bytes per smem row
static constexpr int ABUF = 128 * LDS_B;          // 34816 B per A buffer

template <int NC, bool RELU>
__global__ void __launch_bounds__(256, 1) gemm_kernel(int srcsel, int dstsel, int g) {
    extern __shared__ char sm[];
    const float* __restrict__ A = (srcsel == 0) ? g_agg : (srcsel == 1) ? g_z : g_h;
    float* __restrict__ O = (dstsel == 0) ? g_agg : (dstsel == 1) ? g_z : g_h;

    constexpr int BBUF = NC * LDS_B;
    constexpr int SM_SC = 0;
    constexpr int SM_SH = 512;
    constexpr int SM_AHI = 1024;
    constexpr int SM_ALO = SM_AHI + ABUF;
    constexpr int SM_BHI = SM_ALO + ABUF;
    constexpr int SM_BLO = SM_BHI + BBUF;
    constexpr int NT = NC / 8;                    // n-tiles of 8

    const uint32_t sb = smem_u32(sm);
    const int tid = threadIdx.x, lane = tid & 31, wid = tid >> 5;
    const int m0 = blockIdx.x * 128;

    float* s_scale = (float*)(sm + SM_SC);
    float* s_shift = (float*)(sm + SM_SH);
    if (tid < NC) { s_scale[tid] = g_scale[g][tid]; s_shift[tid] = g_shift[g][tid]; }

    // ---- stage B hi/lo: 16B chunks, row-major padded ----
    {
        const uint4* bh = (const uint4*)g_whi[g];
        const uint4* bl = (const uint4*)g_wlo[g];
        const int nv = NC * 16;                   // 16 x 16B chunks per 256B row
        for (int i = tid; i < nv; i += 256) {
            int row = i >> 4, w = i & 15;
            *(uint4*)(sm + SM_BHI + row * LDS_B + w * 16) = bh[i];
            *(uint4*)(sm + SM_BLO + row * LDS_B + w * 16) = bl[i];
        }
    }

    // ---- stage A: fp32 rows -> split bf16 hi/lo; warp w rows 16w..16w+15 ----
    for (int it = 0; it < 16; it++) {
        int row = wid * 16 + it;
        int grow = m0 + row;
        float4 f = (grow < NN) ? *(const float4*)(A + (size_t)grow * 128 + lane * 4)
                               : make_float4(0.f, 0.f, 0.f, 0.f);
        uint32_t h0, l0, h1, l1;
        split2(f.x, f.y, h0, l0);
        split2(f.z, f.w, h1, l1);
        *(uint2*)(sm + SM_AHI + row * LDS_B + lane * 8) = make_uint2(h0, h1);
        *(uint2*)(sm + SM_ALO + row * LDS_B + lane * 8) = make_uint2(l0, l1);
    }
    __syncthreads();

    // ---- mainloop: acc[NT][4], 3 split passes over K=128 ----
    float acc[NT][4];
    #pragma unroll
    for (int t = 0; t < NT; t++) { acc[t][0] = acc[t][1] = acc[t][2] = acc[t][3] = 0.f; }

    const int abase = wid * 16;   // warp's row base in A tile
    const uint32_t aoffs[3] = { SM_AHI, SM_AHI, SM_ALO };
    const uint32_t boffs[3] = { SM_BHI, SM_BLO, SM_BHI };

    // ldmatrix address precompute (per-lane row/col pieces)
    const int a_m = lane >> 3, a_rr = lane & 7;
    const int a_row = abase + ((a_m & 1) ? 8 : 0) + a_rr;
    const int a_col8 = (a_m >> 1) ? 8 : 0;
    const int b_q = lane >> 3, b_rr = lane & 7;    // q: 0..3 -> (tile pair half, k half)
    const int b_trow = (b_q >> 1) * 8 + b_rr;      // row within a 2-tile (16-row) group
    const int b_col8 = (b_q & 1) ? 8 : 0;

    #pragma unroll
    for (int pass = 0; pass < 3; pass++) {
        const uint32_t pa = sb + aoffs[pass];
        const uint32_t pb = sb + boffs[pass];
        #pragma unroll
        for (int k0 = 0; k0 < 128; k0 += 16) {
            uint32_t a[4];
            ldsm4(a[0], a[1], a[2], a[3],
                  pa + a_row * LDS_B + (k0 + a_col8) * 2);
            #pragma unroll
            for (int t = 0; t < NT; t += 2) {
                uint32_t b0, b1, b2, b3;
                ldsm4(b0, b1, b2, b3,
                      pb + (t * 8 + b_trow) * LDS_B + (k0 + b_col8) * 2);
                mma16816(acc[t],     a, b0, b1);
                mma16816(acc[t + 1], a, b2, b3);
            }
        }
    }

    // ---- epilogue: scale/shift (+relu), fp32 stores ----
    const int gq = lane >> 2, tig = lane & 3;
    const int row0 = m0 + abase + gq;
    const int row1 = row0 + 8;
    #pragma unroll
    for (int t = 0; t < NT; t++) {
        int col = t * 8 + tig * 2;
        float sc0 = s_scale[col], sc1 = s_scale[col + 1];
        float sh0 = s_shift[col], sh1 = s_shift[col + 1];
        float2 o0, o1;
        o0.x = acc[t][0] * sc0 + sh0;  o0.y = acc[t][1] * sc1 + sh1;
        o1.x = acc[t][2] * sc0 + sh0;  o1.y = acc[t][3] * sc1 + sh1;
        if (RELU) {
            o0.x = fmaxf(o0.x, 0.f); o0.y = fmaxf(o0.y, 0.f);
            o1.x = fmaxf(o1.x, 0.f); o1.y = fmaxf(o1.y, 0.f);
        }
        if (row0 < NN) *(float2*)(O + (size_t)row0 * NC + col) = o0;
        if (row1 < NN) *(float2*)(O + (size_t)row1 * NC + col) = o1;
    }
}

// ------------------------- log-softmax (warp per row, logits in g_agg[N][64]) -------------------------
__global__ void lsm_kernel(float* __restrict__ out) {
    int gt = blockIdx.x * blockDim.x + threadIdx.x;
    int rowi = gt >> 5, lane = gt & 31;
    if (rowi >= NN) return;
    const float* row = g_agg + (size_t)rowi * 64;
    float v0 = (lane < CC) ? row[lane] : -INFINITY;
    float v1 = (lane + 32 < CC) ? row[lane + 32] : -INFINITY;
    float m = fmaxf(v0, v1);
    #pragma unroll
    for (int d = 16; d; d >>= 1) m = fmaxf(m, __shfl_xor_sync(0xffffffffu, m, d));
    float s = ((lane < CC) ? expf(v0 - m) : 0.f) + ((lane + 32 < CC) ? expf(v1 - m) : 0.f);
    #pragma unroll
    for (int d = 16; d; d >>= 1) s += __shfl_xor_sync(0xffffffffu, s, d);
    float lse = m + logf(s);
    if (lane < CC) out[(size_t)rowi * CC + lane] = v0 - lse;
    if (lane + 32 < CC) out[(size_t)rowi * CC + lane + 32] = v1 - lse;
}

// ------------------------- launch -------------------------
extern "C" void kernel_launch(void* const* d_in, const int* in_sizes, int n_in,
                              void* d_out, int out_size) {
    const float* x     = (const float*)d_in[0];
    const int*   ei    = (const int*)d_in[1];
    const float* W1    = (const float*)d_in[2];
    const float* b1    = (const float*)d_in[3];
    const float* gamma = (const float*)d_in[4];
    const float* beta  = (const float*)d_in[5];
    const float* mean  = (const float*)d_in[6];
    const float* var   = (const float*)d_in[7];
    const float* W2    = (const float*)d_in[8];
    const float* b2    = (const float*)d_in[9];
    const float* lw1   = (const float*)d_in[10];
    const float* lb1   = (const float*)d_in[11];
    const float* lw2   = (const float*)d_in[12];
    const float* lb2   = (const float*)d_in[13];
    float* out = (float*)d_out;
    const int* src = ei;
    const int* dst = ei + EE;

    const int SMEM128 = 1024 + 2 * ABUF + 2 * 128 * LDS_B;   // 140288
    const int SMEM64  = 1024 + 2 * ABUF + 2 * 64 * LDS_B;    // 105472
    cudaFuncSetAttribute(gemm_kernel<128, true>, cudaFuncAttributeMaxDynamicSharedMemorySize, SMEM128);
    cudaFuncSetAttribute(gemm_kernel<64, false>, cudaFuncAttributeMaxDynamicSharedMemorySize, SMEM64);

    const int MTILES = (NN + 127) / 128;   // 391

    prep_kernel<<<8, 256>>>(W1, b1, gamma, beta, mean, var, W2, b2, lw1, lb1, lw2, lb2);
    zero_kernel<<<(NN + 255) / 256, 256>>>();
    hist_kernel<<<(EE + 255) / 256, 256>>>(dst);
    scan_kernel<<<1, 1024>>>();
    scatter_kernel<<<(EE + 255) / 256, 256>>>(src, dst);

    const int AGG_BLOCKS = (NN * 32 + 255) / 256;
    for (int i = 0; i < 3; i++) {
        agg_kernel<<<AGG_BLOCKS, 256>>>(x, i == 0 ? 1 : 0);
        gemm_kernel<128, true><<<MTILES, 256, SMEM128>>>(0, 1, 2 * i);      // agg -> z (BN+relu)
        gemm_kernel<128, true><<<MTILES, 256, SMEM128>>>(1, 2, 2 * i + 1);  // z -> h (relu)
    }
    gemm_kernel<128, true><<<MTILES, 256, SMEM128>>>(2, 1, 6);              // head1: h -> z
    gemm_kernel<64, false><<<MTILES, 256, SMEM64>>>(1, 0, 7);               // head2: z -> agg[N][64]
    lsm_kernel<<<AGG_BLOCKS, 256>>>(out);
}

// round 14
// speedup vs baseline: 1.1778x; 1.1778x over previous
#include <cuda_runtime.h>
#include <cuda_bf16.h>
#include <cstdint>

#define NN 50000
#define EE 800000
#define FF 128
#define CC 47

// ------------------------- device scratch -------------------------
__device__ float g_agg[NN * FF];
__device__ float g_z[NN * FF];
__device__ float g_h[NN * FF];
__device__ int g_cnt[NN];
__device__ int g_off[NN + 1];
__device__ int g_cur[NN];
__device__ int g_csr[EE];

static constexpr int SBLK = 512;
static constexpr int NB = (NN + SBLK - 1) / SBLK;   // 98
__device__ int g_bsum[NB];
__device__ int g_boff[NB + 1];

// weight blobs: [8 gemms][N<=128 rows][K=128 cols] bf16, row-major [n][k] (B^T)
__device__ __align__(16) __nv_bfloat16 g_whi[8][128 * 128];
__device__ __align__(16) __nv_bfloat16 g_wlo[8][128 * 128];
__device__ float g_scale[8][128];
__device__ float g_shift[8][128];

// ------------------------- PTX helpers -------------------------
__device__ __forceinline__ uint32_t smem_u32(const void* p) {
    uint32_t a;
    asm("{ .reg .u64 t; cvta.to.shared.u64 t, %1; cvt.u32.u64 %0, t; }" : "=r"(a) : "l"(p));
    return a;
}
__device__ __forceinline__ void ldsm4(uint32_t& r0, uint32_t& r1, uint32_t& r2, uint32_t& r3,
                                      uint32_t addr) {
    asm volatile("ldmatrix.sync.aligned.m8n8.x4.shared.b16 {%0,%1,%2,%3}, [%4];"
                 : "=r"(r0), "=r"(r1), "=r"(r2), "=r"(r3) : "r"(addr));
}
__device__ __forceinline__ void mma16816(float* c, const uint32_t* a, uint32_t b0, uint32_t b1) {
    asm volatile(
        "mma.sync.aligned.m16n8k16.row.col.f32.bf16.bf16.f32 "
        "{%0,%1,%2,%3}, {%4,%5,%6,%7}, {%8,%9}, {%0,%1,%2,%3};"
        : "+f"(c[0]), "+f"(c[1]), "+f"(c[2]), "+f"(c[3])
        : "r"(a[0]), "r"(a[1]), "r"(a[2]), "r"(a[3]), "r"(b0), "r"(b1));
}
__device__ __forceinline__ void split2(float a, float b, uint32_t& hi, uint32_t& lo) {
    __nv_bfloat16 ha = __float2bfloat16(a), hb = __float2bfloat16(b);
    __nv_bfloat16 la = __float2bfloat16(a - __bfloat162float(ha));
    __nv_bfloat16 lb = __float2bfloat16(b - __bfloat162float(hb));
    hi = (uint32_t)__bfloat16_as_ushort(ha) | ((uint32_t)__bfloat16_as_ushort(hb) << 16);
    lo = (uint32_t)__bfloat16_as_ushort(la) | ((uint32_t)__bfloat16_as_ushort(lb) << 16);
}

// ------------------------- CSR build -------------------------
__global__ void zero_kernel() {
    int i = blockIdx.x * blockDim.x + threadIdx.x;
    if (i < NN) g_cnt[i] = 0;
}
__global__ void hist_kernel(const int* __restrict__ dst) {
    int e = blockIdx.x * blockDim.x + threadIdx.x;
    if (e < EE) atomicAdd(&g_cnt[dst[e]], 1);
}
// multi-block scan, stage 1: block-local exclusive scan + block sums
__global__ void scan1_kernel() {
    __shared__ int ws[16];
    int t = threadIdx.x, lane = t & 31, wid = t >> 5;
    int i = blockIdx.x * SBLK + t;
    int v = (i < NN) ? g_cnt[i] : 0;
    int x = v;
    #pragma unroll
    for (int d = 1; d < 32; d <<= 1) {
        int y = __shfl_up_sync(0xffffffffu, x, d);
        if (lane >= d) x += y;
    }
    if (lane == 31) ws[wid] = x;
    __syncthreads();
    if (wid == 0 && lane < 16) {
        int s = ws[lane];
        #pragma unroll
        for (int d = 1; d < 16; d <<= 1) {
            int y = __shfl_up_sync(0x0000ffffu, s, d);
            if (lane >= d) s += y;
        }
        ws[lane] = s;
    }
    __syncthreads();
    int pre = (wid > 0) ? ws[wid - 1] : 0;
    if (i < NN) g_off[i] = pre + x - v;
    if (t == SBLK - 1) g_bsum[blockIdx.x] = pre + x;
}
// stage 2: exclusive scan of 98 block sums (one small block)
__global__ void scan2_kernel() {
    __shared__ int ws[4];
    int t = threadIdx.x, lane = t & 31, wid = t >> 5;   // 128 threads
    int v = (t < NB) ? g_bsum[t] : 0;
    int x = v;
    #pragma unroll
    for (int d = 1; d < 32; d <<= 1) {
        int y = __shfl_up_sync(0xffffffffu, x, d);
        if (lane >= d) x += y;
    }
    if (lane == 31) ws[wid] = x;
    __syncthreads();
    if (t == 0) {
        int s = 0;
        #pragma unroll
        for (int w = 0; w < 4; w++) { int tmp = ws[w]; ws[w] = s; s += tmp; }
    }
    __syncthreads();
    int excl = ws[wid] + x - v;
    if (t < NB) g_boff[t] = excl;
    if (t == NB - 1) g_boff[NB] = excl + v;
}
// stage 3: add block offsets, init cursors, total
__global__ void scan3_kernel() {
    int i = blockIdx.x * blockDim.x + threadIdx.x;
    if (i < NN) {
        int o = g_off[i] + g_boff[i / SBLK];
        g_off[i] = o;
        g_cur[i] = o;
    }
    if (i == 0) g_off[NN] = g_boff[NB];
}
__global__ void scatter_kernel(const int* __restrict__ src, const int* __restrict__ dst) {
    int e = blockIdx.x * blockDim.x + threadIdx.x;
    if (e < EE) {
        int p = atomicAdd(&g_cur[dst[e]], 1);
        g_csr[p] = src[e];
    }
}

// ------------------------- aggregation (warp per node) -------------------------
__device__ __forceinline__ void add4(float4& a, const float4& b) {
    a.x += b.x; a.y += b.y; a.z += b.z; a.w += b.w;
}
__global__ void agg_kernel(const float* __restrict__ x, int layer0) {
    const float* __restrict__ hin = layer0 ? x : g_h;
    int gt = blockIdx.x * blockDim.x + threadIdx.x;
    int node = gt >> 5, lane = gt & 31;
    if (node >= NN) return;
    int s = g_off[node], e = g_off[node + 1];
    float4 a0 = *(const float4*)(hin + (size_t)node * FF + lane * 4);  // self term
    float4 a1 = make_float4(0.f, 0.f, 0.f, 0.f);
    int j = s;
    for (; j + 4 <= e; j += 4) {
        int n0 = g_csr[j], n1 = g_csr[j + 1], n2 = g_csr[j + 2], n3 = g_csr[j + 3];
        float4 v0 = *(const float4*)(hin + (size_t)n0 * FF + lane * 4);
        float4 v1 = *(const float4*)(hin + (size_t)n1 * FF + lane * 4);
        float4 v2 = *(const float4*)(hin + (size_t)n2 * FF + lane * 4);
        float4 v3 = *(const float4*)(hin + (size_t)n3 * FF + lane * 4);
        add4(a0, v0); add4(a1, v1); add4(a0, v2); add4(a1, v3);
    }
    for (; j < e; j++) {
        float4 v = *(const float4*)(hin + (size_t)g_csr[j] * FF + lane * 4);
        add4(a0, v);
    }
    add4(a0, a1);
    *(float4*)(g_agg + (size_t)node * FF + lane * 4) = a0;
}

// ------------------------- weight prep: split/transpose + folded BN -------------------------
__global__ void prep_kernel(const float* __restrict__ W1, const float* __restrict__ b1,
                            const float* __restrict__ gamma, const float* __restrict__ beta,
                            const float* __restrict__ mean, const float* __restrict__ var,
                            const float* __restrict__ W2, const float* __restrict__ b2,
                            const float* __restrict__ lw1, const float* __restrict__ lb1,
                            const float* __restrict__ lw2, const float* __restrict__ lb2) {
    int g = blockIdx.x;          // 0..7
    int tid = threadIdx.x;
    int rows = (g == 7) ? 64 : 128;     // N dimension of this gemm's output
    for (int idx = tid; idx < rows * 128; idx += blockDim.x) {
        int n = idx >> 7, k = idx & 127;
        float v;
        if (g < 6) {
            int li = g >> 1;
            const float* W = (g & 1) ? W2 : W1;
            v = W[((size_t)li * 128 + k) * 128 + n];
        } else if (g == 6) {
            v = lw1[k * 128 + n];
        } else {
            v = (n < CC) ? lw2[k * CC + n] : 0.f;
        }
        __nv_bfloat16 h = __float2bfloat16(v);
        __nv_bfloat16 l = __float2bfloat16(v - __bfloat162float(h));
        g_whi[g][n * 128 + k] = h;    // B^T: [n][k] row-major
        g_wlo[g][n * 128 + k] = l;
    }
    if (tid < 128) {
        float sc = 1.f, sh = 0.f;
        if (g < 6) {
            int li = g >> 1, c = li * 128 + tid;
            if ((g & 1) == 0) {
                float rs = rsqrtf(var[c] + 1e-5f);
                sc = gamma[c] * rs;
                sh = beta[c] + (b1[c] - mean[c]) * sc;
            } else {
                sh = b2[c];
            }
        } else if (g == 6) {
            sh = lb1[tid];
        } else {
            sh = (tid < CC) ? lb2[tid] : 0.f;
        }
        g_scale[g][tid] = sc;
        g_shift[g][tid] = sh;
    }
}

// ------------------------- mma.sync GEMM: [128 x 128] @ [128 x NC] ---------------------------
// Split-bf16 emulation fused in a single K loop: D = Ah*Bh + Ah*Bl + Al*Bh (fp32 accum).
// 4x2 warp partition: warp = (wm, wn); wm in 0..3 owns 32 rows, wn in 0..1 owns NC/2 cols.
// smem row stride 272 B (conflict-free ldmatrix: 8 rows at +272B -> banks 0,4,..,28).
static constexpr int LDS_B = 272;
static constexpr int ABUF = 128 * LDS_B;          // 34816 B per A buffer

template <int NC, bool RELU>
__global__ void __launch_bounds__(256, 1) gemm_kernel(int srcsel, int dstsel, int g) {
    extern __shared__ char sm[];
    const float* __restrict__ A = (srcsel == 0) ? g_agg : (srcsel == 1) ? g_z : g_h;
    float* __restrict__ O = (dstsel == 0) ? g_agg : (dstsel == 1) ? g_z : g_h;

    constexpr int BBUF = NC * LDS_B;
    constexpr int SM_SC = 0;
    constexpr int SM_SH = 512;
    constexpr int SM_AHI = 1024;
    constexpr int SM_ALO = SM_AHI + ABUF;
    constexpr int SM_BHI = SM_ALO + ABUF;
    constexpr int SM_BLO = SM_BHI + BBUF;
    constexpr int NWC = NC / 2;                   // cols per warp
    constexpr int NT = NWC / 8;                   // n-tiles of 8 per warp

    const uint32_t sb = smem_u32(sm);
    const int tid = threadIdx.x, lane = tid & 31, wid = tid >> 5;
    const int wm = wid & 3, wn = wid >> 2;
    const int m0 = blockIdx.x * 128;

    float* s_scale = (float*)(sm + SM_SC);
    float* s_shift = (float*)(sm + SM_SH);
    if (tid < NC) { s_scale[tid] = g_scale[g][tid]; s_shift[tid] = g_shift[g][tid]; }

    // ---- stage B hi/lo ----
    {
        const uint4* bh = (const uint4*)g_whi[g];
        const uint4* bl = (const uint4*)g_wlo[g];
        const int nv = NC * 16;
        for (int i = tid; i < nv; i += 256) {
            int row = i >> 4, w = i & 15;
            *(uint4*)(sm + SM_BHI + row * LDS_B + w * 16) = bh[i];
            *(uint4*)(sm + SM_BLO + row * LDS_B + w * 16) = bl[i];
        }
    }
    // ---- stage A: fp32 rows -> split bf16 hi/lo ----
    for (int it = 0; it < 16; it++) {
        int row = wid * 16 + it;
        int grow = m0 + row;
        float4 f = (grow < NN) ? *(const float4*)(A + (size_t)grow * 128 + lane * 4)
                               : make_float4(0.f, 0.f, 0.f, 0.f);
        uint32_t h0, l0, h1, l1;
        split2(f.x, f.y, h0, l0);
        split2(f.z, f.w, h1, l1);
        *(uint2*)(sm + SM_AHI + row * LDS_B + lane * 8) = make_uint2(h0, h1);
        *(uint2*)(sm + SM_ALO + row * LDS_B + lane * 8) = make_uint2(l0, l1);
    }
    __syncthreads();

    // ---- fused mainloop ----
    float acc[2][NT][4];
    #pragma unroll
    for (int mt = 0; mt < 2; mt++)
        #pragma unroll
        for (int t = 0; t < NT; t++)
            acc[mt][t][0] = acc[mt][t][1] = acc[mt][t][2] = acc[mt][t][3] = 0.f;

    const int a_m = lane >> 3, a_rr = lane & 7;
    const int a_row_off = ((a_m & 1) ? 8 : 0) + a_rr;     // within a 16-row tile
    const int a_col8 = (a_m >> 1) ? 8 : 0;
    const int b_q = lane >> 3, b_rr = lane & 7;
    const int b_trow = (b_q >> 1) * 8 + b_rr;             // within a 16-row (2 n-tile) group
    const int b_col8 = (b_q & 1) ? 8 : 0;

    const uint32_t pah = sb + SM_AHI, pal = sb + SM_ALO;
    const uint32_t pbh = sb + SM_BHI, pbl = sb + SM_BLO;

    #pragma unroll
    for (int k0 = 0; k0 < 128; k0 += 16) {
        uint32_t ah[2][4], al[2][4];
        #pragma unroll
        for (int mt = 0; mt < 2; mt++) {
            int row = wm * 32 + mt * 16 + a_row_off;
            uint32_t ro = row * LDS_B + (k0 + a_col8) * 2;
            ldsm4(ah[mt][0], ah[mt][1], ah[mt][2], ah[mt][3], pah + ro);
            ldsm4(al[mt][0], al[mt][1], al[mt][2], al[mt][3], pal + ro);
        }
        #pragma unroll
        for (int t = 0; t < NT; t += 2) {
            int brow = wn * NWC + t * 8 + b_trow;
            uint32_t bo = brow * LDS_B + (k0 + b_col8) * 2;
            uint32_t bh0, bh1, bh2, bh3, bl0, bl1, bl2, bl3;
            ldsm4(bh0, bh1, bh2, bh3, pbh + bo);
            ldsm4(bl0, bl1, bl2, bl3, pbl + bo);
            #pragma unroll
            for (int mt = 0; mt < 2; mt++) {
                mma16816(acc[mt][t],     ah[mt], bh0, bh1);
                mma16816(acc[mt][t + 1], ah[mt], bh2, bh3);
                mma16816(acc[mt][t],     ah[mt], bl0, bl1);
                mma16816(acc[mt][t + 1], ah[mt], bl2, bl3);
                mma16816(acc[mt][t],     al[mt], bh0, bh1);
                mma16816(acc[mt][t + 1], al[mt], bh2, bh3);
            }
        }
    }

    // ---- epilogue: scale/shift (+relu), fp32 stores ----
    const int gq = lane >> 2, tig = lane & 3;
    #pragma unroll
    for (int mt = 0; mt < 2; mt++) {
        int row0 = m0 + wm * 32 + mt * 16 + gq;
        int row1 = row0 + 8;
        #pragma unroll
        for (int t = 0; t < NT; t++) {
            int col = wn * NWC + t * 8 + tig * 2;
            float sc0 = s_scale[col], sc1 = s_scale[col + 1];
            float sh0 = s_shift[col], sh1 = s_shift[col + 1];
            float2 o0, o1;
            o0.x = acc[mt][t][0] * sc0 + sh0;  o0.y = acc[mt][t][1] * sc1 + sh1;
            o1.x = acc[mt][t][2] * sc0 + sh0;  o1.y = acc[mt][t][3] * sc1 + sh1;
            if (RELU) {
                o0.x = fmaxf(o0.x, 0.f); o0.y = fmaxf(o0.y, 0.f);
                o1.x = fmaxf(o1.x, 0.f); o1.y = fmaxf(o1.y, 0.f);
            }
            if (row0 < NN) *(float2*)(O + (size_t)row0 * NC + col) = o0;
            if (row1 < NN) *(float2*)(O + (size_t)row1 * NC + col) = o1;
        }
    }
}

// ------------------------- log-softmax (warp per row, logits in g_agg[N][64]) -------------------------
__global__ void lsm_kernel(float* __restrict__ out) {
    int gt = blockIdx.x * blockDim.x + threadIdx.x;
    int rowi = gt >> 5, lane = gt & 31;
    if (rowi >= NN) return;
    const float* row = g_agg + (size_t)rowi * 64;
    float v0 = (lane < CC) ? row[lane] : -INFINITY;
    float v1 = (lane + 32 < CC) ? row[lane + 32] : -INFINITY;
    float m = fmaxf(v0, v1);
    #pragma unroll
    for (int d = 16; d; d >>= 1) m = fmaxf(m, __shfl_xor_sync(0xffffffffu, m, d));
    float s = ((lane < CC) ? expf(v0 - m) : 0.f) + ((lane + 32 < CC) ? expf(v1 - m) : 0.f);
    #pragma unroll
    for (int d = 16; d; d >>= 1) s += __shfl_xor_sync(0xffffffffu, s, d);
    float lse = m + logf(s);
    if (lane < CC) out[(size_t)rowi * CC + lane] = v0 - lse;
    if (lane + 32 < CC) out[(size_t)rowi * CC + lane + 32] = v1 - lse;
}

// ------------------------- launch -------------------------
extern "C" void kernel_launch(void* const* d_in, const int* in_sizes, int n_in,
                              void* d_out, int out_size) {
    const float* x     = (const float*)d_in[0];
    const int*   ei    = (const int*)d_in[1];
    const float* W1    = (const float*)d_in[2];
    const float* b1    = (const float*)d_in[3];
    const float* gamma = (const float*)d_in[4];
    const float* beta  = (const float*)d_in[5];
    const float* mean  = (const float*)d_in[6];
    const float* var   = (const float*)d_in[7];
    const float* W2    = (const float*)d_in[8];
    const float* b2    = (const float*)d_in[9];
    const float* lw1   = (const float*)d_in[10];
    const float* lb1   = (const float*)d_in[11];
    const float* lw2   = (const float*)d_in[12];
    const float* lb2   = (const float*)d_in[13];
    float* out = (float*)d_out;
    const int* src = ei;
    const int* dst = ei + EE;

    const int SMEM128 = 1024 + 2 * ABUF + 2 * 128 * LDS_B;   // 140288
    const int SMEM64  = 1024 + 2 * ABUF + 2 * 64 * LDS_B;    // 105472
    cudaFuncSetAttribute(gemm_kernel<128, true>, cudaFuncAttributeMaxDynamicSharedMemorySize, SMEM128);
    cudaFuncSetAttribute(gemm_kernel<64, false>, cudaFuncAttributeMaxDynamicSharedMemorySize, SMEM64);

    const int MTILES = (NN + 127) / 128;   // 391

    prep_kernel<<<8, 256>>>(W1, b1, gamma, beta, mean, var, W2, b2, lw1, lb1, lw2, lb2);
    zero_kernel<<<(NN + 255) / 256, 256>>>();
    hist_kernel<<<(EE + 255) / 256, 256>>>(dst);
    scan1_kernel<<<NB, SBLK>>>();
    scan2_kernel<<<1, 128>>>();
    scan3_kernel<<<(NN + 255) / 256, 256>>>();
    scatter_kernel<<<(EE + 255) / 256, 256>>>(src, dst);

    const int AGG_BLOCKS = (NN * 32 + 255) / 256;
    for (int i = 0; i < 3; i++) {
        agg_kernel<<<AGG_BLOCKS, 256>>>(x, i == 0 ? 1 : 0);
        gemm_kernel<128, true><<<MTILES, 256, SMEM128>>>(0, 1, 2 * i);      // agg -> z (BN+relu)
        gemm_kernel<128, true><<<MTILES, 256, SMEM128>>>(1, 2, 2 * i + 1);  // z -> h (relu)
    }
    gemm_kernel<128, true><<<MTILES, 256, SMEM128>>>(2, 1, 6);              // head1: h -> z
    gemm_kernel<64, false><<<MTILES, 256, SMEM64>>>(1, 0, 7);               // head2: z -> agg[N][64]
    lsm_kernel<<<AGG_BLOCKS, 256>>>(out);
}

// round 15
// speedup vs baseline: 1.3310x; 1.1300x over previous
#include <cuda_runtime.h>
#include <cuda_bf16.h>
#include <cstdint>

#define NN 50000
#define EE 800000
#define FF 128
#define CC 47

// ------------------------- device scratch -------------------------
__device__ float g_agg[NN * FF];
__device__ float g_h[NN * FF];
__device__ int g_cnt[NN];
__device__ int g_off[NN + 1];
__device__ int g_cur[NN];
__device__ int g_csr[EE];

static constexpr int SBLK = 512;
static constexpr int NB = (NN + SBLK - 1) / SBLK;   // 98
__device__ int g_bsum[NB];
__device__ int g_boff[NB + 1];

// weight blobs: [8 gemms][N<=128 rows][K=128 cols] bf16, row-major [n][k] (B^T)
__device__ __align__(16) __nv_bfloat16 g_whi[8][128 * 128];
__device__ __align__(16) __nv_bfloat16 g_wlo[8][128 * 128];
__device__ float g_scale[8][128];
__device__ float g_shift[8][128];

// ------------------------- PTX helpers -------------------------
__device__ __forceinline__ uint32_t smem_u32(const void* p) {
    uint32_t a;
    asm("{ .reg .u64 t; cvta.to.shared.u64 t, %1; cvt.u32.u64 %0, t; }" : "=r"(a) : "l"(p));
    return a;
}
__device__ __forceinline__ void ldsm4(uint32_t& r0, uint32_t& r1, uint32_t& r2, uint32_t& r3,
                                      uint32_t addr) {
    asm volatile("ldmatrix.sync.aligned.m8n8.x4.shared.b16 {%0,%1,%2,%3}, [%4];"
                 : "=r"(r0), "=r"(r1), "=r"(r2), "=r"(r3) : "r"(addr));
}
__device__ __forceinline__ void mma16816(float* c, const uint32_t* a, uint32_t b0, uint32_t b1) {
    asm volatile(
        "mma.sync.aligned.m16n8k16.row.col.f32.bf16.bf16.f32 "
        "{%0,%1,%2,%3}, {%4,%5,%6,%7}, {%8,%9}, {%0,%1,%2,%3};"
        : "+f"(c[0]), "+f"(c[1]), "+f"(c[2]), "+f"(c[3])
        : "r"(a[0]), "r"(a[1]), "r"(a[2]), "r"(a[3]), "r"(b0), "r"(b1));
}
__device__ __forceinline__ void split2(float a, float b, uint32_t& hi, uint32_t& lo) {
    __nv_bfloat16 ha = __float2bfloat16(a), hb = __float2bfloat16(b);
    __nv_bfloat16 la = __float2bfloat16(a - __bfloat162float(ha));
    __nv_bfloat16 lb = __float2bfloat16(b - __bfloat162float(hb));
    hi = (uint32_t)__bfloat16_as_ushort(ha) | ((uint32_t)__bfloat16_as_ushort(hb) << 16);
    lo = (uint32_t)__bfloat16_as_ushort(la) | ((uint32_t)__bfloat16_as_ushort(lb) << 16);
}

// ------------------------- CSR build -------------------------
__global__ void zero_kernel() {
    int i = blockIdx.x * blockDim.x + threadIdx.x;
    if (i < NN) g_cnt[i] = 0;
}
__global__ void hist_kernel(const int* __restrict__ dst) {
    int e = blockIdx.x * blockDim.x + threadIdx.x;
    if (e < EE) atomicAdd(&g_cnt[dst[e]], 1);
}
__global__ void scan1_kernel() {
    __shared__ int ws[16];
    int t = threadIdx.x, lane = t & 31, wid = t >> 5;
    int i = blockIdx.x * SBLK + t;
    int v = (i < NN) ? g_cnt[i] : 0;
    int x = v;
    #pragma unroll
    for (int d = 1; d < 32; d <<= 1) {
        int y = __shfl_up_sync(0xffffffffu, x, d);
        if (lane >= d) x += y;
    }
    if (lane == 31) ws[wid] = x;
    __syncthreads();
    if (wid == 0 && lane < 16) {
        int s = ws[lane];
        #pragma unroll
        for (int d = 1; d < 16; d <<= 1) {
            int y = __shfl_up_sync(0x0000ffffu, s, d);
            if (lane >= d) s += y;
        }
        ws[lane] = s;
    }
    __syncthreads();
    int pre = (wid > 0) ? ws[wid - 1] : 0;
    if (i < NN) g_off[i] = pre + x - v;
    if (t == SBLK - 1) g_bsum[blockIdx.x] = pre + x;
}
__global__ void scan2_kernel() {
    __shared__ int ws[4];
    int t = threadIdx.x, lane = t & 31, wid = t >> 5;   // 128 threads
    int v = (t < NB) ? g_bsum[t] : 0;
    int x = v;
    #pragma unroll
    for (int d = 1; d < 32; d <<= 1) {
        int y = __shfl_up_sync(0xffffffffu, x, d);
        if (lane >= d) x += y;
    }
    if (lane == 31) ws[wid] = x;
    __syncthreads();
    if (t == 0) {
        int s = 0;
        #pragma unroll
        for (int w = 0; w < 4; w++) { int tmp = ws[w]; ws[w] = s; s += tmp; }
    }
    __syncthreads();
    int excl = ws[wid] + x - v;
    if (t < NB) g_boff[t] = excl;
    if (t == NB - 1) g_boff[NB] = excl + v;
}
__global__ void scan3_kernel() {
    int i = blockIdx.x * blockDim.x + threadIdx.x;
    if (i < NN) {
        int o = g_off[i] + g_boff[i / SBLK];
        g_off[i] = o;
        g_cur[i] = o;
    }
    if (i == 0) g_off[NN] = g_boff[NB];
}
__global__ void scatter_kernel(const int* __restrict__ src, const int* __restrict__ dst) {
    int e = blockIdx.x * blockDim.x + threadIdx.x;
    if (e < EE) {
        int p = atomicAdd(&g_cur[dst[e]], 1);
        g_csr[p] = src[e];
    }
}

// ------------------------- aggregation (warp per node) -------------------------
__device__ __forceinline__ void add4(float4& a, const float4& b) {
    a.x += b.x; a.y += b.y; a.z += b.z; a.w += b.w;
}
__global__ void agg_kernel(const float* __restrict__ x, int layer0) {
    const float* __restrict__ hin = layer0 ? x : g_h;
    int gt = blockIdx.x * blockDim.x + threadIdx.x;
    int node = gt >> 5, lane = gt & 31;
    if (node >= NN) return;
    int s = g_off[node], e = g_off[node + 1];
    float4 a0 = *(const float4*)(hin + (size_t)node * FF + lane * 4);  // self term
    float4 a1 = make_float4(0.f, 0.f, 0.f, 0.f);
    int j = s;
    for (; j + 4 <= e; j += 4) {
        int n0 = g_csr[j], n1 = g_csr[j + 1], n2 = g_csr[j + 2], n3 = g_csr[j + 3];
        float4 v0 = *(const float4*)(hin + (size_t)n0 * FF + lane * 4);
        float4 v1 = *(const float4*)(hin + (size_t)n1 * FF + lane * 4);
        float4 v2 = *(const float4*)(hin + (size_t)n2 * FF + lane * 4);
        float4 v3 = *(const float4*)(hin + (size_t)n3 * FF + lane * 4);
        add4(a0, v0); add4(a1, v1); add4(a0, v2); add4(a1, v3);
    }
    for (; j < e; j++) {
        float4 v = *(const float4*)(hin + (size_t)g_csr[j] * FF + lane * 4);
        add4(a0, v);
    }
    add4(a0, a1);
    *(float4*)(g_agg + (size_t)node * FF + lane * 4) = a0;
}

// ------------------------- weight prep: split/transpose + folded BN -------------------------
__global__ void prep_kernel(const float* __restrict__ W1, const float* __restrict__ b1,
                            const float* __restrict__ gamma, const float* __restrict__ beta,
                            const float* __restrict__ mean, const float* __restrict__ var,
                            const float* __restrict__ W2, const float* __restrict__ b2,
                            const float* __restrict__ lw1, const float* __restrict__ lb1,
                            const float* __restrict__ lw2, const float* __restrict__ lb2) {
    int g = blockIdx.x;          // 0..7
    int tid = threadIdx.x;
    int rows = (g == 7) ? 64 : 128;     // N dimension of this gemm's output
    for (int idx = tid; idx < rows * 128; idx += blockDim.x) {
        int n = idx >> 7, k = idx & 127;
        float v;
        if (g < 6) {
            int li = g >> 1;
            const float* W = (g & 1) ? W2 : W1;
            v = W[((size_t)li * 128 + k) * 128 + n];
        } else if (g == 6) {
            v = lw1[k * 128 + n];
        } else {
            v = (n < CC) ? lw2[k * CC + n] : 0.f;
        }
        __nv_bfloat16 h = __float2bfloat16(v);
        __nv_bfloat16 l = __float2bfloat16(v - __bfloat162float(h));
        g_whi[g][n * 128 + k] = h;    // B^T: [n][k] row-major
        g_wlo[g][n * 128 + k] = l;
    }
    if (tid < 128) {
        float sc = 1.f, sh = 0.f;
        if (g < 6) {
            int li = g >> 1, c = li * 128 + tid;
            if ((g & 1) == 0) {
                float rs = rsqrtf(var[c] + 1e-5f);
                sc = gamma[c] * rs;
                sh = beta[c] + (b1[c] - mean[c]) * sc;
            } else {
                sh = b2[c];
            }
        } else if (g == 6) {
            sh = lb1[tid];
        } else {
            sh = (tid < CC) ? lb2[tid] : 0.f;
        }
        g_scale[g][tid] = sc;
        g_shift[g][tid] = sh;
    }
}

// ------------------------- fused double-GEMM building blocks -------------------------
// smem row stride 272 B (conflict-free ldmatrix: 8 rows at +272B -> banks 0,4,..,28).
static constexpr int LDS_B = 272;
static constexpr int ABUF = 128 * LDS_B;          // 34816 B

// smem layout (fused kernels)
static constexpr int SM_SC1 = 0;
static constexpr int SM_SH1 = 512;
static constexpr int SM_SC2 = 1024;
static constexpr int SM_SH2 = 1536;
static constexpr int SM_AHI = 2048;
static constexpr int SM_ALO = SM_AHI + ABUF;          // 36864
static constexpr int SM_B1HI = SM_ALO + ABUF;         // 71680
static constexpr int SM_B1LO = SM_B1HI + ABUF;        // 106496
static constexpr int SM_B2HI = SM_B1LO + ABUF;        // 141312
// MLP: B2 is 128 rows; HEAD: B2 is 64 rows
static constexpr int SMEM_MLP  = SM_B2HI + 2 * ABUF;              // 210944
static constexpr int SMEM_HEAD = SM_B2HI + 2 * (64 * LDS_B);      // 176128
static constexpr int SM_LOGITS = SM_AHI;   // head: reuse A buffer for logits (128*64*4 = 32768)

// fused mainloop over K=128: D = Ah*Bh + Ah*Bl + Al*Bh
template <int NT>
__device__ __forceinline__ void mainloop(uint32_t pah, uint32_t pal,
                                         uint32_t pbh, uint32_t pbl,
                                         int wm, int wn, int lane,
                                         float acc[2][NT][4]) {
    #pragma unroll
    for (int mt = 0; mt < 2; mt++)
        #pragma unroll
        for (int t = 0; t < NT; t++)
            acc[mt][t][0] = acc[mt][t][1] = acc[mt][t][2] = acc[mt][t][3] = 0.f;

    const int a_m = lane >> 3, a_rr = lane & 7;
    const int a_row_off = ((a_m & 1) ? 8 : 0) + a_rr;
    const int a_col8 = (a_m >> 1) ? 8 : 0;
    const int b_q = lane >> 3, b_rr = lane & 7;
    const int b_trow = (b_q >> 1) * 8 + b_rr;
    const int b_col8 = (b_q & 1) ? 8 : 0;
    constexpr int NWC = NT * 8;

    #pragma unroll
    for (int k0 = 0; k0 < 128; k0 += 16) {
        uint32_t ah[2][4], al[2][4];
        #pragma unroll
        for (int mt = 0; mt < 2; mt++) {
            int row = wm * 32 + mt * 16 + a_row_off;
            uint32_t ro = row * LDS_B + (k0 + a_col8) * 2;
            ldsm4(ah[mt][0], ah[mt][1], ah[mt][2], ah[mt][3], pah + ro);
            ldsm4(al[mt][0], al[mt][1], al[mt][2], al[mt][3], pal + ro);
        }
        #pragma unroll
        for (int t = 0; t < NT; t += 2) {
            int brow = wn * NWC + t * 8 + b_trow;
            uint32_t bo = brow * LDS_B + (k0 + b_col8) * 2;
            uint32_t bh0, bh1, bh2, bh3, bl0, bl1, bl2, bl3;
            ldsm4(bh0, bh1, bh2, bh3, pbh + bo);
            ldsm4(bl0, bl1, bl2, bl3, pbl + bo);
            #pragma unroll
            for (int mt = 0; mt < 2; mt++) {
                mma16816(acc[mt][t],     ah[mt], bh0, bh1);
                mma16816(acc[mt][t + 1], ah[mt], bh2, bh3);
                mma16816(acc[mt][t],     ah[mt], bl0, bl1);
                mma16816(acc[mt][t + 1], ah[mt], bl2, bl3);
                mma16816(acc[mt][t],     al[mt], bh0, bh1);
                mma16816(acc[mt][t + 1], al[mt], bh2, bh3);
            }
        }
    }
}

__device__ __forceinline__ void stage_b(char* sm, int smoff_hi, int smoff_lo,
                                        int g, int rows, int tid) {
    const uint4* bh = (const uint4*)g_whi[g];
    const uint4* bl = (const uint4*)g_wlo[g];
    const int nv = rows * 16;
    for (int i = tid; i < nv; i += 256) {
        int row = i >> 4, w = i & 15;
        *(uint4*)(sm + smoff_hi + row * LDS_B + w * 16) = bh[i];
        *(uint4*)(sm + smoff_lo + row * LDS_B + w * 16) = bl[i];
    }
}

// ------------------------- fused MLP layer: relu(BN(agg@W1+b1)) @ W2 + b2, relu -> g_h -------------
__global__ void __launch_bounds__(256, 1) mlp_kernel(int g1, int g2) {
    extern __shared__ char sm[];
    const uint32_t sb = smem_u32(sm);
    const int tid = threadIdx.x, lane = tid & 31, wid = tid >> 5;
    const int wm = wid & 3, wn = wid >> 2;
    const int m0 = blockIdx.x * 128;

    float* s_sc1 = (float*)(sm + SM_SC1);
    float* s_sh1 = (float*)(sm + SM_SH1);
    float* s_sc2 = (float*)(sm + SM_SC2);
    float* s_sh2 = (float*)(sm + SM_SH2);
    if (tid < 128) {
        s_sc1[tid] = g_scale[g1][tid]; s_sh1[tid] = g_shift[g1][tid];
        s_sc2[tid] = g_scale[g2][tid]; s_sh2[tid] = g_shift[g2][tid];
    }

    stage_b(sm, SM_B1HI, SM_B1LO, g1, 128, tid);
    stage_b(sm, SM_B2HI, SM_B2HI + ABUF, g2, 128, tid);

    // stage A from g_agg
    for (int it = 0; it < 16; it++) {
        int row = wid * 16 + it;
        int grow = m0 + row;
        float4 f = (grow < NN) ? *(const float4*)(g_agg + (size_t)grow * 128 + lane * 4)
                               : make_float4(0.f, 0.f, 0.f, 0.f);
        uint32_t h0, l0, h1, l1;
        split2(f.x, f.y, h0, l0);
        split2(f.z, f.w, h1, l1);
        *(uint2*)(sm + SM_AHI + row * LDS_B + lane * 8) = make_uint2(h0, h1);
        *(uint2*)(sm + SM_ALO + row * LDS_B + lane * 8) = make_uint2(l0, l1);
    }
    __syncthreads();

    float acc[2][8][4];
    mainloop<8>(sb + SM_AHI, sb + SM_ALO, sb + SM_B1HI, sb + SM_B1LO, wm, wn, lane, acc);
    __syncthreads();   // everyone done reading A before z overwrites it

    // epilogue1: z = relu(acc*sc1+sh1), split to bf16, write back into A buffers
    const int gq = lane >> 2, tig = lane & 3;
    #pragma unroll
    for (int mt = 0; mt < 2; mt++) {
        int r0 = wm * 32 + mt * 16 + gq;
        #pragma unroll
        for (int t = 0; t < 8; t++) {
            int col = wn * 64 + t * 8 + tig * 2;
            float sc0 = s_sc1[col], sc1v = s_sc1[col + 1];
            float sh0 = s_sh1[col], sh1v = s_sh1[col + 1];
            float z00 = fmaxf(acc[mt][t][0] * sc0 + sh0, 0.f);
            float z01 = fmaxf(acc[mt][t][1] * sc1v + sh1v, 0.f);
            float z10 = fmaxf(acc[mt][t][2] * sc0 + sh0, 0.f);
            float z11 = fmaxf(acc[mt][t][3] * sc1v + sh1v, 0.f);
            uint32_t h0, l0, h1, l1;
            split2(z00, z01, h0, l0);
            split2(z10, z11, h1, l1);
            uint32_t o0 = r0 * LDS_B + col * 2;
            uint32_t o1 = (r0 + 8) * LDS_B + col * 2;
            *(uint32_t*)(sm + SM_AHI + o0) = h0;
            *(uint32_t*)(sm + SM_ALO + o0) = l0;
            *(uint32_t*)(sm + SM_AHI + o1) = h1;
            *(uint32_t*)(sm + SM_ALO + o1) = l1;
        }
    }
    __syncthreads();

    mainloop<8>(sb + SM_AHI, sb + SM_ALO, sb + SM_B2HI, sb + SM_B2HI + ABUF, wm, wn, lane, acc);

    // epilogue2: h = relu(acc + b2) -> g_h
    #pragma unroll
    for (int mt = 0; mt < 2; mt++) {
        int row0 = m0 + wm * 32 + mt * 16 + gq;
        int row1 = row0 + 8;
        #pragma unroll
        for (int t = 0; t < 8; t++) {
            int col = wn * 64 + t * 8 + tig * 2;
            float sh0 = s_sh2[col], sh1v = s_sh2[col + 1];
            float2 o0, o1;
            o0.x = fmaxf(acc[mt][t][0] + sh0, 0.f);  o0.y = fmaxf(acc[mt][t][1] + sh1v, 0.f);
            o1.x = fmaxf(acc[mt][t][2] + sh0, 0.f);  o1.y = fmaxf(acc[mt][t][3] + sh1v, 0.f);
            if (row0 < NN) *(float2*)(g_h + (size_t)row0 * 128 + col) = o0;
            if (row1 < NN) *(float2*)(g_h + (size_t)row1 * 128 + col) = o1;
        }
    }
}

// ------------------------- fused head: relu(h@lw1+lb1) @ lw2 + lb2 -> log_softmax -> out -------------
__global__ void __launch_bounds__(256, 1) head_kernel(float* __restrict__ out) {
    extern __shared__ char sm[];
    const uint32_t sb = smem_u32(sm);
    const int tid = threadIdx.x, lane = tid & 31, wid = tid >> 5;
    const int wm = wid & 3, wn = wid >> 2;
    const int m0 = blockIdx.x * 128;

    float* s_sh1 = (float*)(sm + SM_SH1);
    float* s_sh2 = (float*)(sm + SM_SH2);
    if (tid < 128) { s_sh1[tid] = g_shift[6][tid]; }
    if (tid < 64)  { s_sh2[tid] = g_shift[7][tid]; }

    stage_b(sm, SM_B1HI, SM_B1LO, 6, 128, tid);
    stage_b(sm, SM_B2HI, SM_B2HI + 64 * LDS_B, 7, 64, tid);

    for (int it = 0; it < 16; it++) {
        int row = wid * 16 + it;
        int grow = m0 + row;
        float4 f = (grow < NN) ? *(const float4*)(g_h + (size_t)grow * 128 + lane * 4)
                               : make_float4(0.f, 0.f, 0.f, 0.f);
        uint32_t h0, l0, h1, l1;
        split2(f.x, f.y, h0, l0);
        split2(f.z, f.w, h1, l1);
        *(uint2*)(sm + SM_AHI + row * LDS_B + lane * 8) = make_uint2(h0, h1);
        *(uint2*)(sm + SM_ALO + row * LDS_B + lane * 8) = make_uint2(l0, l1);
    }
    __syncthreads();

    float acc[2][8][4];
    mainloop<8>(sb + SM_AHI, sb + SM_ALO, sb + SM_B1HI, sb + SM_B1LO, wm, wn, lane, acc);
    __syncthreads();

    const int gq = lane >> 2, tig = lane & 3;
    #pragma unroll
    for (int mt = 0; mt < 2; mt++) {
        int r0 = wm * 32 + mt * 16 + gq;
        #pragma unroll
        for (int t = 0; t < 8; t++) {
            int col = wn * 64 + t * 8 + tig * 2;
            float sh0 = s_sh1[col], sh1v = s_sh1[col + 1];
            float z00 = fmaxf(acc[mt][t][0] + sh0, 0.f);
            float z01 = fmaxf(acc[mt][t][1] + sh1v, 0.f);
            float z10 = fmaxf(acc[mt][t][2] + sh0, 0.f);
            float z11 = fmaxf(acc[mt][t][3] + sh1v, 0.f);
            uint32_t h0, l0, h1, l1;
            split2(z00, z01, h0, l0);
            split2(z10, z11, h1, l1);
            uint32_t o0 = r0 * LDS_B + col * 2;
            uint32_t o1 = (r0 + 8) * LDS_B + col * 2;
            *(uint32_t*)(sm + SM_AHI + o0) = h0;
            *(uint32_t*)(sm + SM_ALO + o0) = l0;
            *(uint32_t*)(sm + SM_AHI + o1) = h1;
            *(uint32_t*)(sm + SM_ALO + o1) = l1;
        }
    }
    __syncthreads();

    // GEMM2: NC=64 (NT=4 per warp)
    float acc2[2][4][4];
    mainloop<4>(sb + SM_AHI, sb + SM_ALO, sb + SM_B2HI, sb + SM_B2HI + 64 * LDS_B, wm, wn, lane, acc2);
    __syncthreads();   // done reading A -> reuse as logits tile

    // logits -> smem [128 rows x 64 cols] fp32
    float* s_log = (float*)(sm + SM_LOGITS);
    #pragma unroll
    for (int mt = 0; mt < 2; mt++) {
        int r0 = wm * 32 + mt * 16 + gq;
        #pragma unroll
        for (int t = 0; t < 4; t++) {
            int col = wn * 32 + t * 8 + tig * 2;
            float sh0 = s_sh2[col], sh1v = s_sh2[col + 1];
            s_log[r0 * 64 + col]           = acc2[mt][t][0] + sh0;
            s_log[r0 * 64 + col + 1]       = acc2[mt][t][1] + sh1v;
            s_log[(r0 + 8) * 64 + col]     = acc2[mt][t][2] + sh0;
            s_log[(r0 + 8) * 64 + col + 1] = acc2[mt][t][3] + sh1v;
        }
    }
    __syncthreads();

    // log-softmax: warp per row, 16 rows per warp
    for (int r = wid; r < 128; r += 8) {
        int grow = m0 + r;
        if (grow >= NN) break;
        const float* row = s_log + r * 64;
        float v0 = (lane < CC) ? row[lane] : -INFINITY;
        float v1 = (lane + 32 < CC) ? row[lane + 32] : -INFINITY;
        float m = fmaxf(v0, v1);
        #pragma unroll
        for (int d = 16; d; d >>= 1) m = fmaxf(m, __shfl_xor_sync(0xffffffffu, m, d));
        float s = ((lane < CC) ? expf(v0 - m) : 0.f) + ((lane + 32 < CC) ? expf(v1 - m) : 0.f);
        #pragma unroll
        for (int d = 16; d; d >>= 1) s += __shfl_xor_sync(0xffffffffu, s, d);
        float lse = m + logf(s);
        if (lane < CC) out[(size_t)grow * CC + lane] = v0 - lse;
        if (lane + 32 < CC) out[(size_t)grow * CC + lane + 32] = v1 - lse;
    }
}

// ------------------------- launch -------------------------
extern "C" void kernel_launch(void* const* d_in, const int* in_sizes, int n_in,
                              void* d_out, int out_size) {
    const float* x     = (const float*)d_in[0];
    const int*   ei    = (const int*)d_in[1];
    const float* W1    = (const float*)d_in[2];
    const float* b1    = (const float*)d_in[3];
    const float* gamma = (const float*)d_in[4];
    const float* beta  = (const float*)d_in[5];
    const float* mean  = (const float*)d_in[6];
    const float* var   = (const float*)d_in[7];
    const float* W2    = (const float*)d_in[8];
    const float* b2    = (const float*)d_in[9];
    const float* lw1   = (const float*)d_in[10];
    const float* lb1   = (const float*)d_in[11];
    const float* lw2   = (const float*)d_in[12];
    const float* lb2   = (const float*)d_in[13];
    float* out = (float*)d_out;
    const int* src = ei;
    const int* dst = ei + EE;

    cudaFuncSetAttribute(mlp_kernel, cudaFuncAttributeMaxDynamicSharedMemorySize, SMEM_MLP);
    cudaFuncSetAttribute(head_kernel, cudaFuncAttributeMaxDynamicSharedMemorySize, SMEM_HEAD);

    const int MTILES = (NN + 127) / 128;   // 391

    prep_kernel<<<8, 256>>>(W1, b1, gamma, beta, mean, var, W2, b2, lw1, lb1, lw2, lb2);
    zero_kernel<<<(NN + 255) / 256, 256>>>();
    hist_kernel<<<(EE + 255) / 256, 256>>>(dst);
    scan1_kernel<<<NB, SBLK>>>();
    scan2_kernel<<<1, 128>>>();
    scan3_kernel<<<(NN + 255) / 256, 256>>>();
    scatter_kernel<<<(EE + 255) / 256, 256>>>(src, dst);

    const int AGG_BLOCKS = (NN * 32 + 255) / 256;
    for (int i = 0; i < 3; i++) {
        agg_kernel<<<AGG_BLOCKS, 256>>>(x, i == 0 ? 1 : 0);
        mlp_kernel<<<MTILES, 256, SMEM_MLP>>>(2 * i, 2 * i + 1);
    }
    head_kernel<<<MTILES, 256, SMEM_HEAD>>>(out);
}